// round 1
// baseline (speedup 1.0000x reference)
#include <cuda_runtime.h>
#include <cstdint>

#define NNODES 100000
#define FDIM 192
#define NHEAD 3
#define HDIM 64
#define MRF 266
#define MPAD 272          // padded random-feature dim (mult of 16), pad entries are exactly 0
#define NLAYER 4
#define EEDGE 1000000
#define EPSK 1e-3f
#define LNEPS 1e-5f

#define CHN 1024                       // nodes per kv-partial block
#define NCHUNK ((NNODES + CHN - 1) / CHN)   // 98

// ---------------- scratch (device globals; no allocation allowed) ----------------
__device__ float g_q[(size_t)NNODES * FDIM];
__device__ float g_k[(size_t)NNODES * FDIM];
__device__ float g_v[(size_t)NNODES * FDIM];
__device__ float g_qf[(size_t)NHEAD * NNODES * MPAD];
__device__ float g_kf[(size_t)NHEAD * NNODES * MPAD];
__device__ float g_attn[(size_t)NNODES * FDIM];
__device__ float g_tmp[(size_t)NNODES * FDIM];
__device__ float g_h[(size_t)NNODES * FDIM];
__device__ float g_kvp[(size_t)NHEAD * NCHUNK * HDIM * MPAD];
__device__ float g_ksp[(size_t)NHEAD * NCHUNK * MPAD];
__device__ float g_kvT[NHEAD * HDIM * MPAD];   // B-operand layout [head][d][m]
__device__ float g_ksum[NHEAD * MPAD];

// ---------------- generic tiled GEMM: C[n][o] = sum_k A[n][k] * B[o][k] -----------
// MODE 0: plain    MODE 1: relu(x)+eps for o<oreal else 0 (performer feature map)
// MODE 2: FAVOR+ epilogue: scale row n by 1/(sum_k A[n][k]*aux[k])  (aux = ksum)
// MODE 3: + aux[o] (bias)
template <int MODE>
__global__ __launch_bounds__(256) void gemm_kernel(
    const float* __restrict__ A, int lda,
    const float* __restrict__ B, int ldb, int brows,
    float* __restrict__ C, int ldc,
    int nrows, int K, int O, int oreal,
    const float* __restrict__ aux)
{
    __shared__ float As[16][64];
    __shared__ float Bs[16][64];
    __shared__ float ks_s[16];
    __shared__ float sdinv[64];

    const int tx = threadIdx.x & 15;   // output-col group
    const int ty = threadIdx.x >> 4;   // output-row group
    const int n0 = blockIdx.y * 64;
    const int o0 = blockIdx.x * 64;

    const int lrow = threadIdx.x >> 2;   // 0..63
    const int lc4  = threadIdx.x & 3;    // 0..3

    float acc[4][4] = {};
    float dacc[4] = {0.f, 0.f, 0.f, 0.f};

    for (int kb = 0; kb < K; kb += 16) {
        // --- load A tile (64 rows x 16 k), transposed to As[k][n]
        {
            float4 av = make_float4(0.f, 0.f, 0.f, 0.f);
            int n = n0 + lrow;
            if (n < nrows)
                av = *(const float4*)&A[(size_t)n * lda + kb + lc4 * 4];
            As[lc4 * 4 + 0][lrow] = av.x;
            As[lc4 * 4 + 1][lrow] = av.y;
            As[lc4 * 4 + 2][lrow] = av.z;
            As[lc4 * 4 + 3][lrow] = av.w;
        }
        // --- load B tile (64 o-rows x 16 k), transposed to Bs[k][o]
        {
            float4 bv = make_float4(0.f, 0.f, 0.f, 0.f);
            int o = o0 + lrow;
            if (o < brows)
                bv = *(const float4*)&B[(size_t)o * ldb + kb + lc4 * 4];
            Bs[lc4 * 4 + 0][lrow] = bv.x;
            Bs[lc4 * 4 + 1][lrow] = bv.y;
            Bs[lc4 * 4 + 2][lrow] = bv.z;
            Bs[lc4 * 4 + 3][lrow] = bv.w;
        }
        if (MODE == 2 && threadIdx.x < 16)
            ks_s[threadIdx.x] = aux[kb + threadIdx.x];
        __syncthreads();

#pragma unroll
        for (int k = 0; k < 16; k++) {
            float4 a = *(const float4*)&As[k][ty * 4];
            float4 b = *(const float4*)&Bs[k][tx * 4];
            float ar[4] = {a.x, a.y, a.z, a.w};
            float br[4] = {b.x, b.y, b.z, b.w};
#pragma unroll
            for (int i = 0; i < 4; i++)
#pragma unroll
                for (int j = 0; j < 4; j++)
                    acc[i][j] += ar[i] * br[j];
            if (MODE == 2 && tx == 0) {
                float ksv = ks_s[k];
#pragma unroll
                for (int i = 0; i < 4; i++) dacc[i] += ar[i] * ksv;
            }
        }
        __syncthreads();
    }

    if (MODE == 2) {
        if (tx == 0) {
#pragma unroll
            for (int i = 0; i < 4; i++)
                sdinv[ty * 4 + i] = 1.0f / dacc[i];
        }
        __syncthreads();
    }

#pragma unroll
    for (int i = 0; i < 4; i++) {
        int n = n0 + ty * 4 + i;
        if (n >= nrows) continue;
        float dinv = (MODE == 2) ? sdinv[ty * 4 + i] : 1.0f;
#pragma unroll
        for (int j = 0; j < 4; j++) {
            int o = o0 + tx * 4 + j;
            if (o >= O) continue;
            float v = acc[i][j];
            if (MODE == 1) v = (o < oreal) ? (fmaxf(v, 0.f) + EPSK) : 0.f;
            if (MODE == 2) v *= dinv;
            if (MODE == 3) v += aux[o];
            C[(size_t)n * ldc + o] = v;
        }
    }
}

// ---------------- kv partial: kvT_part[d][m] = sum_{n in chunk} kf[n][m]*v[n][d] ---
__global__ __launch_bounds__(256) void kv_partial_kernel()
{
    const int head = blockIdx.y;
    const int chunk = blockIdx.x;
    const float* __restrict__ kf = g_kf + (size_t)head * NNODES * MPAD;

    extern __shared__ float sm[];
    float* kf_s = sm;               // 64 * 272
    float* v_s  = sm + 64 * MPAD;   // 64 * 64

    const int tm = threadIdx.x & 63;   // m group
    const int tg = threadIdx.x >> 6;   // d group (0..3)

    float acc[5][16];
#pragma unroll
    for (int j = 0; j < 5; j++)
#pragma unroll
        for (int d = 0; d < 16; d++) acc[j][d] = 0.f;
    float ks[5] = {0.f, 0.f, 0.f, 0.f, 0.f};

    const int nbase0 = chunk * CHN;
    for (int sub = 0; sub < CHN / 64; sub++) {
        const int nb = nbase0 + sub * 64;
        __syncthreads();
        // load kf tile: 64 x 272 floats = 4352 float4, 17 per thread (coalesced)
#pragma unroll
        for (int i = 0; i < 17; i++) {
            int idx = threadIdx.x + 256 * i;
            int r = idx / 68, c4 = idx % 68;
            float4 val = make_float4(0.f, 0.f, 0.f, 0.f);
            if (nb + r < NNODES)
                val = *(const float4*)&kf[(size_t)(nb + r) * MPAD + c4 * 4];
            *(float4*)&kf_s[r * MPAD + c4 * 4] = val;
        }
        // load v tile: 64 x 64 = 1024 float4, 4 per thread
#pragma unroll
        for (int i = 0; i < 4; i++) {
            int idx = threadIdx.x + 256 * i;
            int r = idx >> 4, c4 = idx & 15;
            float4 val = make_float4(0.f, 0.f, 0.f, 0.f);
            if (nb + r < NNODES)
                val = *(const float4*)&g_v[(size_t)(nb + r) * FDIM + head * HDIM + c4 * 4];
            *(float4*)&v_s[r * 64 + c4 * 4] = val;
        }
        __syncthreads();

        for (int c = 0; c < 64; c++) {
            float kr[5];
#pragma unroll
            for (int j = 0; j < 5; j++) {
                int m = tm + 64 * j;
                kr[j] = (m < MPAD) ? kf_s[c * MPAD + m] : 0.f;
            }
            float vr[16];
#pragma unroll
            for (int jj = 0; jj < 4; jj++)
                *(float4*)&vr[jj * 4] = *(const float4*)&v_s[c * 64 + tg * 16 + jj * 4];
#pragma unroll
            for (int j = 0; j < 5; j++)
#pragma unroll
                for (int d = 0; d < 16; d++)
                    acc[j][d] += kr[j] * vr[d];
            if (tg == 0) {
#pragma unroll
                for (int j = 0; j < 5; j++) ks[j] += kr[j];
            }
        }
    }

    float* out = g_kvp + (size_t)(head * NCHUNK + chunk) * HDIM * MPAD;
#pragma unroll
    for (int j = 0; j < 5; j++) {
        int m = tm + 64 * j;
        if (m < MPAD)
#pragma unroll
            for (int d = 0; d < 16; d++)
                out[(size_t)(tg * 16 + d) * MPAD + m] = acc[j][d];
    }
    if (tg == 0) {
        float* outk = g_ksp + (size_t)(head * NCHUNK + chunk) * MPAD;
#pragma unroll
        for (int j = 0; j < 5; j++) {
            int m = tm + 64 * j;
            if (m < MPAD) outk[m] = ks[j];
        }
    }
}

// ---------------- deterministic split-K reduction ----------------
__global__ void kv_reduce_kernel()
{
    int idx = blockIdx.x * blockDim.x + threadIdx.x;
    const int per_head = (HDIM + 1) * MPAD;
    if (idx >= NHEAD * per_head) return;
    int head = idx / per_head;
    int rem = idx % per_head;
    float s = 0.f;
    if (rem < HDIM * MPAD) {
        for (int c = 0; c < NCHUNK; c++)
            s += g_kvp[(size_t)(head * NCHUNK + c) * HDIM * MPAD + rem];
        g_kvT[head * HDIM * MPAD + rem] = s;
    } else {
        int m = rem - HDIM * MPAD;
        for (int c = 0; c < NCHUNK; c++)
            s += g_ksp[(size_t)(head * NCHUNK + c) * MPAD + m];
        g_ksum[head * MPAD + m] = s;
    }
}

// ---------------- LayerNorm (+optional relu), one warp per node ----------------
__global__ void ln_kernel(const float* __restrict__ in, float* __restrict__ out,
                          const float* __restrict__ gamma, const float* __restrict__ beta,
                          int relu)
{
    int node = blockIdx.x * (blockDim.x >> 5) + (threadIdx.x >> 5);
    int lane = threadIdx.x & 31;
    if (node >= NNODES) return;
    const float* row = in + (size_t)node * FDIM;
    float x[6];
    float s = 0.f;
#pragma unroll
    for (int i = 0; i < 6; i++) { x[i] = row[lane + 32 * i]; s += x[i]; }
#pragma unroll
    for (int o = 16; o; o >>= 1) s += __shfl_xor_sync(0xffffffffu, s, o);
    float mu = s * (1.0f / FDIM);
    float v = 0.f;
#pragma unroll
    for (int i = 0; i < 6; i++) { float d = x[i] - mu; v += d * d; }
#pragma unroll
    for (int o = 16; o; o >>= 1) v += __shfl_xor_sync(0xffffffffu, v, o);
    v *= (1.0f / FDIM);
    float inv = rsqrtf(v + LNEPS);
    float* orow = out + (size_t)node * FDIM;
#pragma unroll
    for (int i = 0; i < 6; i++) {
        int o = lane + 32 * i;
        float y = (x[i] - mu) * inv * gamma[o] + beta[o];
        if (relu) y = fmaxf(y, 0.f);
        orow[o] = y;
    }
}

// ---------------- launch ----------------
extern "C" void kernel_launch(void* const* d_in, const int* in_sizes, int n_in,
                              void* d_out, int out_size)
{
    const float* h0    = (const float*)d_in[0];
    const float* eattr = (const float*)d_in[1];
    // d_in[2] = edge_index (int64) -- unused by the reference computation
    const float* Wq = (const float*)d_in[3];
    const float* Wk = (const float*)d_in[4];
    const float* Wv = (const float*)d_in[5];
    const float* Wo = (const float*)d_in[6];
    const float* bo = (const float*)d_in[7];
    const float* ga = (const float*)d_in[8];
    const float* be = (const float*)d_in[9];
    const float* pr = (const float*)d_in[10];
    float* out = (float*)d_out;

    float *q, *k, *v, *qf, *kf, *attn, *tmp, *hbuf, *kvT, *ksum;
    cudaGetSymbolAddress((void**)&q, g_q);
    cudaGetSymbolAddress((void**)&k, g_k);
    cudaGetSymbolAddress((void**)&v, g_v);
    cudaGetSymbolAddress((void**)&qf, g_qf);
    cudaGetSymbolAddress((void**)&kf, g_kf);
    cudaGetSymbolAddress((void**)&attn, g_attn);
    cudaGetSymbolAddress((void**)&tmp, g_tmp);
    cudaGetSymbolAddress((void**)&hbuf, g_h);
    cudaGetSymbolAddress((void**)&kvT, g_kvT);
    cudaGetSymbolAddress((void**)&ksum, g_ksum);

    const int kv_smem = (64 * MPAD + 64 * 64) * (int)sizeof(float);   // 86016 B
    cudaFuncSetAttribute(kv_partial_kernel,
                         cudaFuncAttributeMaxDynamicSharedMemorySize, kv_smem);

    // pass-through edge_attr to second output slot
    cudaMemcpyAsync(out + (size_t)NNODES * FDIM, eattr,
                    (size_t)EEDGE * 8 * sizeof(float), cudaMemcpyDeviceToDevice);

    const int NB = (NNODES + 63) / 64;   // 1563
    const dim3 gFF(FDIM / 64, NB);       // 3 x 1563
    const dim3 gQF((MPAD + 63) / 64, NB);   // 5 x 1563
    const dim3 gOUT(1, NB);

    for (int l = 0; l < NLAYER; l++) {
        const float* hin  = (l == 0) ? h0 : hbuf;
        float* hout = (l == NLAYER - 1) ? out : hbuf;
        const float* wq = Wq + (size_t)l * FDIM * FDIM;
        const float* wk = Wk + (size_t)l * FDIM * FDIM;
        const float* wv = Wv + (size_t)l * FDIM * FDIM;
        const float* wo = Wo + (size_t)l * FDIM * FDIM;
        const float* pj = pr + (size_t)l * MRF * HDIM;

        gemm_kernel<0><<<gFF, 256>>>(hin, FDIM, wq, FDIM, FDIM, q, FDIM,
                                     NNODES, FDIM, FDIM, FDIM, nullptr);
        gemm_kernel<0><<<gFF, 256>>>(hin, FDIM, wk, FDIM, FDIM, k, FDIM,
                                     NNODES, FDIM, FDIM, FDIM, nullptr);
        gemm_kernel<0><<<gFF, 256>>>(hin, FDIM, wv, FDIM, FDIM, v, FDIM,
                                     NNODES, FDIM, FDIM, FDIM, nullptr);

        for (int hh = 0; hh < NHEAD; hh++) {
            gemm_kernel<1><<<gQF, 256>>>(q + hh * HDIM, FDIM, pj, HDIM, MRF,
                                         qf + (size_t)hh * NNODES * MPAD, MPAD,
                                         NNODES, HDIM, MPAD, MRF, nullptr);
            gemm_kernel<1><<<gQF, 256>>>(k + hh * HDIM, FDIM, pj, HDIM, MRF,
                                         kf + (size_t)hh * NNODES * MPAD, MPAD,
                                         NNODES, HDIM, MPAD, MRF, nullptr);
        }

        kv_partial_kernel<<<dim3(NCHUNK, NHEAD), 256, kv_smem>>>();
        kv_reduce_kernel<<<(NHEAD * (HDIM + 1) * MPAD + 255) / 256, 256>>>();

        for (int hh = 0; hh < NHEAD; hh++) {
            gemm_kernel<2><<<gOUT, 256>>>(qf + (size_t)hh * NNODES * MPAD, MPAD,
                                          kvT + hh * HDIM * MPAD, MPAD, HDIM,
                                          attn + hh * HDIM, FDIM,
                                          NNODES, MPAD, HDIM, HDIM,
                                          ksum + hh * MPAD);
        }

        gemm_kernel<3><<<gFF, 256>>>(attn, FDIM, wo, FDIM, FDIM, tmp, FDIM,
                                     NNODES, FDIM, FDIM, FDIM, bo + l * FDIM);

        ln_kernel<<<(NNODES + 3) / 4, 128>>>(tmp, hout, ga + l * FDIM, be + l * FDIM,
                                             (l < NLAYER - 1) ? 1 : 0);
    }
}

// round 3
// speedup vs baseline: 1.4118x; 1.4118x over previous
#include <cuda_runtime.h>
#include <mma.h>
#include <cstdint>
using namespace nvcuda;

#define NNODES 100000
#define FDIM 192
#define NHEAD 3
#define HDIM 64
#define MRF 266
#define MPAD 288          // padded random-feature dim (mult of 32), pad entries exactly 0
#define NLAYER 4
#define EEDGE 1000000
#define EPSK 1e-3f
#define LNEPS 1e-5f

#define CHN 1024
#define NCHUNK ((NNODES + CHN - 1) / CHN)   // 98

// ---------------- scratch (device globals; no allocation allowed) ----------------
__device__ float g_q[(size_t)NNODES * FDIM];
__device__ float g_k[(size_t)NNODES * FDIM];
__device__ float g_v[(size_t)NNODES * FDIM];
__device__ float g_qf[(size_t)NHEAD * NNODES * MPAD];
__device__ float g_kf[(size_t)NHEAD * NNODES * MPAD];
__device__ float g_attn[(size_t)NNODES * FDIM];
__device__ float g_tmp[(size_t)NNODES * FDIM];
__device__ float g_h[(size_t)NNODES * FDIM];
__device__ float g_kvp[(size_t)NHEAD * NCHUNK * HDIM * MPAD];
__device__ float g_ksp[(size_t)NHEAD * NCHUNK * MPAD];
__device__ float g_kvT[NHEAD * HDIM * MPAD];   // [head][d][m]
__device__ float g_ksum[NHEAD * MPAD];
__device__ float g_dinv[(size_t)NHEAD * NNODES];

// ======================= TF32 tensor-core GEMM =======================
// C[n][o] = sum_k A[n][k] * B[o][k]      (B row-major [brows][ldb])
// MODE 0: plain
// MODE 1: relu(x)+eps for o<oreal, 0 for oreal<=o<O   (performer feature map)
// MODE 2: scale row n by aux[n]  (precomputed 1/denominator)
// MODE 3: + aux[o] (bias)
// Block tile 128x64, 8 warps (4x2), warp tile 32x32 = 2x2 wmma m16n16k8.
template <int MODE>
__global__ __launch_bounds__(256) void tc_gemm(
    const float* __restrict__ A, int lda,
    const float* __restrict__ B, int ldb, int brows,
    float* __restrict__ C, int ldc,
    int nrows, int K, int O, int oreal,
    const float* __restrict__ aux)
{
    __shared__ union {
        float stage[128 * 36 + 64 * 36];   // As[128][36] ++ Bs[64][36]
        float cst[128 * 68];               // epilogue staging
    } sm;
    float* As = sm.stage;
    float* Bs = sm.stage + 128 * 36;

    const int t = threadIdx.x;
    const int warp = t >> 5;
    const int wr = warp >> 1;   // warp row 0..3
    const int wc = warp & 1;    // warp col 0..1
    const int n0 = blockIdx.y * 128;
    const int o0 = blockIdx.x * 64;

    wmma::fragment<wmma::accumulator, 16, 16, 8, float> cf[2][2];
#pragma unroll
    for (int i = 0; i < 2; i++)
#pragma unroll
        for (int j = 0; j < 2; j++) wmma::fill_fragment(cf[i][j], 0.0f);

    for (int kb = 0; kb < K; kb += 32) {
        __syncthreads();
        // stage A tile 128x32 (tf32-rounded)
#pragma unroll
        for (int i = 0; i < 4; i++) {
            int r = (t >> 3) + i * 32;
            int c4 = (t & 7) * 4;
            int n = n0 + r;
            float4 v = make_float4(0.f, 0.f, 0.f, 0.f);
            if (n < nrows) v = *(const float4*)&A[(size_t)n * lda + kb + c4];
            As[r * 36 + c4 + 0] = wmma::__float_to_tf32(v.x);
            As[r * 36 + c4 + 1] = wmma::__float_to_tf32(v.y);
            As[r * 36 + c4 + 2] = wmma::__float_to_tf32(v.z);
            As[r * 36 + c4 + 3] = wmma::__float_to_tf32(v.w);
        }
        // stage B tile 64x32
#pragma unroll
        for (int i = 0; i < 2; i++) {
            int r = (t >> 3) + i * 32;
            int c4 = (t & 7) * 4;
            int o = o0 + r;
            float4 v = make_float4(0.f, 0.f, 0.f, 0.f);
            if (o < brows) v = *(const float4*)&B[(size_t)o * ldb + kb + c4];
            Bs[r * 36 + c4 + 0] = wmma::__float_to_tf32(v.x);
            Bs[r * 36 + c4 + 1] = wmma::__float_to_tf32(v.y);
            Bs[r * 36 + c4 + 2] = wmma::__float_to_tf32(v.z);
            Bs[r * 36 + c4 + 3] = wmma::__float_to_tf32(v.w);
        }
        __syncthreads();

#pragma unroll
        for (int kk = 0; kk < 4; kk++) {
            wmma::fragment<wmma::matrix_a, 16, 16, 8, wmma::precision::tf32, wmma::row_major> af[2];
            wmma::fragment<wmma::matrix_b, 16, 16, 8, wmma::precision::tf32, wmma::col_major> bf[2];
#pragma unroll
            for (int i = 0; i < 2; i++)
                wmma::load_matrix_sync(af[i], As + (wr * 32 + i * 16) * 36 + kk * 8, 36);
#pragma unroll
            for (int j = 0; j < 2; j++)
                wmma::load_matrix_sync(bf[j], Bs + (wc * 32 + j * 16) * 36 + kk * 8, 36);
#pragma unroll
            for (int i = 0; i < 2; i++)
#pragma unroll
                for (int j = 0; j < 2; j++)
                    wmma::mma_sync(cf[i][j], af[i], bf[j], cf[i][j]);
        }
    }

    __syncthreads();
#pragma unroll
    for (int i = 0; i < 2; i++)
#pragma unroll
        for (int j = 0; j < 2; j++)
            wmma::store_matrix_sync(&sm.cst[(wr * 32 + i * 16) * 68 + wc * 32 + j * 16],
                                    cf[i][j], 68, wmma::mem_row_major);
    __syncthreads();

#pragma unroll
    for (int i = 0; i < 32; i++) {
        int idx = t + i * 256;
        int r = idx >> 6, c = idx & 63;
        int n = n0 + r, o = o0 + c;
        if (n >= nrows || o >= O) continue;
        float v = sm.cst[r * 68 + c];
        if (MODE == 1) v = (o < oreal) ? (fmaxf(v, 0.f) + EPSK) : 0.f;
        if (MODE == 2) v *= aux[n];
        if (MODE == 3) v += aux[o];
        C[(size_t)n * ldc + o] = v;
    }
}

// ---------------- kv partial: kvT_part[d][m] = sum_{n in chunk} kf[n][m]*v[n][d] ---
__global__ __launch_bounds__(256) void kv_partial_kernel()
{
    const int head = blockIdx.y;
    const int chunk = blockIdx.x;
    const float* __restrict__ kf = g_kf + (size_t)head * NNODES * MPAD;

    extern __shared__ float smv[];
    float* kf_s = smv;               // 64 * 288
    float* v_s  = smv + 64 * MPAD;   // 64 * 64

    const int tm = threadIdx.x & 63;
    const int tg = threadIdx.x >> 6;

    float acc[5][16];
#pragma unroll
    for (int j = 0; j < 5; j++)
#pragma unroll
        for (int d = 0; d < 16; d++) acc[j][d] = 0.f;
    float ks[5] = {0.f, 0.f, 0.f, 0.f, 0.f};

    const int nbase0 = chunk * CHN;
    for (int sub = 0; sub < CHN / 64; sub++) {
        const int nb = nbase0 + sub * 64;
        __syncthreads();
        // kf tile: 64 x 288 = 4608 float4 (18 per thread)
#pragma unroll
        for (int i = 0; i < 18; i++) {
            int idx = threadIdx.x + 256 * i;
            int r = idx / 72, c4 = idx % 72;
            float4 val = make_float4(0.f, 0.f, 0.f, 0.f);
            if (nb + r < NNODES)
                val = *(const float4*)&kf[(size_t)(nb + r) * MPAD + c4 * 4];
            *(float4*)&kf_s[r * MPAD + c4 * 4] = val;
        }
        // v tile: 64 x 64
#pragma unroll
        for (int i = 0; i < 4; i++) {
            int idx = threadIdx.x + 256 * i;
            int r = idx >> 4, c4 = idx & 15;
            float4 val = make_float4(0.f, 0.f, 0.f, 0.f);
            if (nb + r < NNODES)
                val = *(const float4*)&g_v[(size_t)(nb + r) * FDIM + head * HDIM + c4 * 4];
            *(float4*)&v_s[r * 64 + c4 * 4] = val;
        }
        __syncthreads();

        for (int c = 0; c < 64; c++) {
            float kr[5];
#pragma unroll
            for (int j = 0; j < 5; j++) {
                int m = tm + 64 * j;
                kr[j] = (m < MPAD) ? kf_s[c * MPAD + m] : 0.f;
            }
            float vr[16];
#pragma unroll
            for (int jj = 0; jj < 4; jj++)
                *(float4*)&vr[jj * 4] = *(const float4*)&v_s[c * 64 + tg * 16 + jj * 4];
#pragma unroll
            for (int j = 0; j < 5; j++)
#pragma unroll
                for (int d = 0; d < 16; d++)
                    acc[j][d] += kr[j] * vr[d];
            if (tg == 0) {
#pragma unroll
                for (int j = 0; j < 5; j++) ks[j] += kr[j];
            }
        }
    }

    float* outp = g_kvp + (size_t)(head * NCHUNK + chunk) * HDIM * MPAD;
#pragma unroll
    for (int j = 0; j < 5; j++) {
        int m = tm + 64 * j;
        if (m < MPAD)
#pragma unroll
            for (int d = 0; d < 16; d++)
                outp[(size_t)(tg * 16 + d) * MPAD + m] = acc[j][d];
    }
    if (tg == 0) {
        float* outk = g_ksp + (size_t)(head * NCHUNK + chunk) * MPAD;
#pragma unroll
        for (int j = 0; j < 5; j++) {
            int m = tm + 64 * j;
            if (m < MPAD) outk[m] = ks[j];
        }
    }
}

// ---------------- deterministic split-K reduction ----------------
__global__ void kv_reduce_kernel()
{
    int idx = blockIdx.x * blockDim.x + threadIdx.x;
    const int per_head = (HDIM + 1) * MPAD;
    if (idx >= NHEAD * per_head) return;
    int head = idx / per_head;
    int rem = idx % per_head;
    float s = 0.f;
    if (rem < HDIM * MPAD) {
        for (int c = 0; c < NCHUNK; c++)
            s += g_kvp[(size_t)(head * NCHUNK + c) * HDIM * MPAD + rem];
        g_kvT[head * HDIM * MPAD + rem] = s;
    } else {
        int m = rem - HDIM * MPAD;
        for (int c = 0; c < NCHUNK; c++)
            s += g_ksp[(size_t)(head * NCHUNK + c) * MPAD + m];
        g_ksum[head * MPAD + m] = s;
    }
}

// ---------------- FAVOR+ denominator: dinv[h,n] = 1/(qf[h,n,:] . ksum[h,:]) -------
__global__ void denom_kernel()
{
    int gw = (blockIdx.x * blockDim.x + threadIdx.x) >> 5;
    int lane = threadIdx.x & 31;
    if (gw >= NHEAD * NNODES) return;
    int h = gw / NNODES, n = gw % NNODES;
    const float* row = g_qf + ((size_t)h * NNODES + n) * MPAD;
    const float* ks = g_ksum + h * MPAD;
    float s = 0.f;
#pragma unroll
    for (int i = 0; i < 9; i++) {
        int m = lane + 32 * i;
        s += row[m] * ks[m];
    }
#pragma unroll
    for (int o = 16; o; o >>= 1) s += __shfl_xor_sync(0xffffffffu, s, o);
    if (lane == 0) g_dinv[(size_t)h * NNODES + n] = 1.0f / s;
}

// ---------------- LayerNorm (+optional relu), one warp per node ----------------
__global__ void ln_kernel(const float* __restrict__ in, float* __restrict__ out,
                          const float* __restrict__ gamma, const float* __restrict__ beta,
                          int relu)
{
    int node = blockIdx.x * (blockDim.x >> 5) + (threadIdx.x >> 5);
    int lane = threadIdx.x & 31;
    if (node >= NNODES) return;
    const float* row = in + (size_t)node * FDIM;
    float x[6];
    float s = 0.f;
#pragma unroll
    for (int i = 0; i < 6; i++) { x[i] = row[lane + 32 * i]; s += x[i]; }
#pragma unroll
    for (int o = 16; o; o >>= 1) s += __shfl_xor_sync(0xffffffffu, s, o);
    float mu = s * (1.0f / FDIM);
    float v = 0.f;
#pragma unroll
    for (int i = 0; i < 6; i++) { float d = x[i] - mu; v += d * d; }
#pragma unroll
    for (int o = 16; o; o >>= 1) v += __shfl_xor_sync(0xffffffffu, v, o);
    v *= (1.0f / FDIM);
    float inv = rsqrtf(v + LNEPS);
    float* orow = out + (size_t)node * FDIM;
#pragma unroll
    for (int i = 0; i < 6; i++) {
        int o = lane + 32 * i;
        float y = (x[i] - mu) * inv * gamma[o] + beta[o];
        if (relu) y = fmaxf(y, 0.f);
        orow[o] = y;
    }
}

// ---------------- launch ----------------
extern "C" void kernel_launch(void* const* d_in, const int* in_sizes, int n_in,
                              void* d_out, int out_size)
{
    const float* h0    = (const float*)d_in[0];
    const float* eattr = (const float*)d_in[1];
    // d_in[2] = edge_index (int64) -- unused by the reference computation
    const float* Wq = (const float*)d_in[3];
    const float* Wk = (const float*)d_in[4];
    const float* Wv = (const float*)d_in[5];
    const float* Wo = (const float*)d_in[6];
    const float* bo = (const float*)d_in[7];
    const float* ga = (const float*)d_in[8];
    const float* be = (const float*)d_in[9];
    const float* pr = (const float*)d_in[10];
    float* out = (float*)d_out;

    float *q, *k, *v, *qf, *kf, *attn, *tmp, *hbuf, *kvT, *ksum, *dinv;
    cudaGetSymbolAddress((void**)&q, g_q);
    cudaGetSymbolAddress((void**)&k, g_k);
    cudaGetSymbolAddress((void**)&v, g_v);
    cudaGetSymbolAddress((void**)&qf, g_qf);
    cudaGetSymbolAddress((void**)&kf, g_kf);
    cudaGetSymbolAddress((void**)&attn, g_attn);
    cudaGetSymbolAddress((void**)&tmp, g_tmp);
    cudaGetSymbolAddress((void**)&hbuf, g_h);
    cudaGetSymbolAddress((void**)&kvT, g_kvT);
    cudaGetSymbolAddress((void**)&ksum, g_ksum);
    cudaGetSymbolAddress((void**)&dinv, g_dinv);

    const int kv_smem = (64 * MPAD + 64 * 64) * (int)sizeof(float);   // 90112 B
    cudaFuncSetAttribute(kv_partial_kernel,
                         cudaFuncAttributeMaxDynamicSharedMemorySize, kv_smem);

    // pass-through edge_attr to second output slot
    cudaMemcpyAsync(out + (size_t)NNODES * FDIM, eattr,
                    (size_t)EEDGE * 8 * sizeof(float), cudaMemcpyDeviceToDevice);

    const int NB128 = (NNODES + 127) / 128;   // 782
    const dim3 gFF(FDIM / 64, NB128);         // 3 x 782
    const dim3 gQF((MPAD + 63) / 64, NB128);  // 5 x 782 (last block partial)
    const dim3 gOUT(1, NB128);

    for (int l = 0; l < NLAYER; l++) {
        const float* hin  = (l == 0) ? h0 : hbuf;
        float* hout = (l == NLAYER - 1) ? out : hbuf;
        const float* wq = Wq + (size_t)l * FDIM * FDIM;
        const float* wk = Wk + (size_t)l * FDIM * FDIM;
        const float* wv = Wv + (size_t)l * FDIM * FDIM;
        const float* wo = Wo + (size_t)l * FDIM * FDIM;
        const float* pj = pr + (size_t)l * MRF * HDIM;

        tc_gemm<0><<<gFF, 256>>>(hin, FDIM, wq, FDIM, FDIM, q, FDIM,
                                 NNODES, FDIM, FDIM, FDIM, nullptr);
        tc_gemm<0><<<gFF, 256>>>(hin, FDIM, wk, FDIM, FDIM, k, FDIM,
                                 NNODES, FDIM, FDIM, FDIM, nullptr);
        tc_gemm<0><<<gFF, 256>>>(hin, FDIM, wv, FDIM, FDIM, v, FDIM,
                                 NNODES, FDIM, FDIM, FDIM, nullptr);

        for (int hh = 0; hh < NHEAD; hh++) {
            tc_gemm<1><<<gQF, 256>>>(q + hh * HDIM, FDIM, pj, HDIM, MRF,
                                     qf + (size_t)hh * NNODES * MPAD, MPAD,
                                     NNODES, HDIM, MPAD, MRF, nullptr);
            tc_gemm<1><<<gQF, 256>>>(k + hh * HDIM, FDIM, pj, HDIM, MRF,
                                     kf + (size_t)hh * NNODES * MPAD, MPAD,
                                     NNODES, HDIM, MPAD, MRF, nullptr);
        }

        kv_partial_kernel<<<dim3(NCHUNK, NHEAD), 256, kv_smem>>>();
        kv_reduce_kernel<<<(NHEAD * (HDIM + 1) * MPAD + 255) / 256, 256>>>();
        denom_kernel<<<(NHEAD * NNODES * 32 + 255) / 256, 256>>>();

        for (int hh = 0; hh < NHEAD; hh++) {
            tc_gemm<2><<<gOUT, 256>>>(qf + (size_t)hh * NNODES * MPAD, MPAD,
                                      kvT + hh * HDIM * MPAD, MPAD, HDIM,
                                      attn + hh * HDIM, FDIM,
                                      NNODES, MPAD, HDIM, HDIM,
                                      dinv + (size_t)hh * NNODES);
        }

        tc_gemm<3><<<gFF, 256>>>(attn, FDIM, wo, FDIM, FDIM, tmp, FDIM,
                                 NNODES, FDIM, FDIM, FDIM, bo + l * FDIM);

        ln_kernel<<<(NNODES + 3) / 4, 128>>>(tmp, hout, ga + l * FDIM, be + l * FDIM,
                                             (l < NLAYER - 1) ? 1 : 0);
    }
}

// round 6
// speedup vs baseline: 3.2593x; 2.3086x over previous
#include <cuda_runtime.h>
#include <cstdint>

#define NNODES 100000
#define FDIM 192
#define NHEAD 3
#define HDIM 64
#define MRF 266
#define MPAD 288
#define QKF 576
#define ROWF 864
#define NLAYER 4
#define EEDGE 1000000
#define EPSK 1e-3f
#define LNEPS 1e-5f
#define CHN 2112
#define NC 48
#define NKV (CHN / 32)
#define NB128 ((NNODES + 127) / 128)

__device__ float g_qkv[(size_t)NNODES * QKF];
__device__ float g_qf[(size_t)NNODES * ROWF + 1024];
__device__ float g_kf[(size_t)NNODES * ROWF + 1024];
__device__ float g_attn[(size_t)NNODES * FDIM];
__device__ float g_tmp[(size_t)NNODES * FDIM];
__device__ float g_h[(size_t)NNODES * FDIM];
__device__ float g_kvp[(size_t)NHEAD * NC * 384 * 64];
__device__ float g_ksp[(size_t)NHEAD * NC * 384];
__device__ float g_kvT[NHEAD * HDIM * MPAD];
__device__ float g_ksum[NHEAD * MPAD];
__device__ float g_wqkv[NLAYER * QKF * FDIM];
__device__ float g_wor[NLAYER * FDIM * FDIM];
__device__ float g_projr[NLAYER * MPAD * HDIM];

__device__ __forceinline__ float rtf(float x) {
    unsigned u; asm("cvt.rna.tf32.f32 %0, %1;" : "=r"(u) : "f"(x));
    return __uint_as_float(u);
}
__device__ __forceinline__ void cpa16(unsigned dst, const float* src, bool p) {
    int sz = p ? 16 : 0;
    asm volatile("cp.async.cg.shared.global [%0], [%1], 16, %2;" :: "r"(dst), "l"(src), "r"(sz));
}
__device__ __forceinline__ void cp_commit() { asm volatile("cp.async.commit_group;"); }
template <int N> __device__ __forceinline__ void cp_wait() {
    asm volatile("cp.async.wait_group %0;" :: "n"(N));
}
__device__ __forceinline__ void mma8(float* c, unsigned a0, unsigned a1, unsigned a2,
                                     unsigned a3, unsigned b0, unsigned b1) {
    asm volatile("mma.sync.aligned.m16n8k8.row.col.f32.tf32.tf32.f32 "
                 "{%0,%1,%2,%3}, {%4,%5,%6,%7}, {%8,%9}, {%0,%1,%2,%3};"
                 : "+f"(c[0]), "+f"(c[1]), "+f"(c[2]), "+f"(c[3])
                 : "r"(a0), "r"(a1), "r"(a2), "r"(a3), "r"(b0), "r"(b1));
}

// stage one 128xBN k-slice (A-tile + B-tile) into shared buffer sA
template <int BN>
__device__ __forceinline__ void stage_gemm(float* sA, const float* A, int lda,
                                           const float* B, int ldb, int brows,
                                           int n0, int o0, int t, int kb)
{
    float* sB = sA + 128 * 36;
    unsigned ua = (unsigned)__cvta_generic_to_shared(sA);
    unsigned ub = (unsigned)__cvta_generic_to_shared(sB);
#pragma unroll
    for (int i = 0; i < 4; i++) {
        int id = t + 256 * i, r = id >> 3, c4 = (id & 7) * 4;
        cpa16(ua + (r * 36 + c4) * 4, A + (size_t)(n0 + r) * lda + kb + c4, (n0 + r) < NNODES);
    }
#pragma unroll
    for (int i = 0; i < BN / 32; i++) {
        int id = t + 256 * i, r = id >> 3, c4 = (id & 7) * 4;
        cpa16(ub + (r * 36 + c4) * 4, B + (size_t)(o0 + r) * ldb + kb + c4, (o0 + r) < brows);
    }
}

// C[n][o] = sum_k A[n][k]*B[o][k].  128 x BN tile, 8 warps (4x2), cp.async 2-stage.
// MODE 0: round-store (QKV)   MODE 1: relu+eps|0 + round (features)
// MODE 2: fused FAVOR+ denom (aux=ksum per head), scale+round   MODE 3: +bias
template <int MODE, int BN>
__global__ __launch_bounds__(256) void tc_gemm2(
    const float* __restrict__ A, int lda,
    const float* __restrict__ B, int ldb, int brows,
    float* __restrict__ C, int ldc,
    int K, int oreal, const float* __restrict__ aux, int aZ, long long cZ)
{
    extern __shared__ float sm[];
    constexpr int STG = (128 + BN) * 36;
    constexpr int NS = BN / 16;
    const int t = threadIdx.x, lane = t & 31, warp = t >> 5;
    const int wr = warp >> 1, wc = warp & 1;
    const int n0 = blockIdx.y * 128, o0 = blockIdx.x * BN;
    A += (size_t)blockIdx.z * aZ;
    C += cZ * blockIdx.z;
    if (MODE == 2) { B += (size_t)blockIdx.z * 64 * K; aux += (size_t)blockIdx.z * K; }
    float* ks_s = sm + 2 * STG;
    float* dinv_s = ks_s + 320;

    if (MODE == 2) {
        for (int i = t; i < K; i += 256) ks_s[i] = aux[i];
    }

    float acc[2][NS][4];
#pragma unroll
    for (int ms = 0; ms < 2; ms++)
#pragma unroll
        for (int ns = 0; ns < NS; ns++)
#pragma unroll
            for (int j = 0; j < 4; j++) acc[ms][ns][j] = 0.f;
    float dot = 0.f;

    const int NK = K >> 5;
    stage_gemm<BN>(sm, A, lda, B, ldb, brows, n0, o0, t, 0);
    cp_commit();
    for (int it = 0; it < NK; it++) {
        if (it + 1 < NK) {
            stage_gemm<BN>(sm + ((it + 1) & 1) * STG, A, lda, B, ldb, brows,
                           n0, o0, t, (it + 1) << 5);
            cp_commit(); cp_wait<1>();
        } else {
            cp_wait<0>();
        }
        __syncthreads();
        float* sA = sm + (it & 1) * STG; float* sB = sA + 128 * 36;

        if (MODE == 2) {
            int rr = t >> 1, kh = (t & 1) * 16;
#pragma unroll
            for (int j = 0; j < 4; j++) {
                float4 av = *(const float4*)&sA[rr * 36 + kh + j * 4];
                float4 kv = *(const float4*)&ks_s[(it << 5) + kh + j * 4];
                dot += av.x * kv.x + av.y * kv.y + av.z * kv.z + av.w * kv.w;
            }
        }
#pragma unroll
        for (int kk = 0; kk < 4; kk++) {
            int k0 = kk * 8;
            unsigned bfr[NS][2];
#pragma unroll
            for (int ns = 0; ns < NS; ns++) {
                int col = wc * (BN / 2) + ns * 8 + (lane >> 2);
                bfr[ns][0] = __float_as_uint(sB[col * 36 + k0 + (lane & 3)]);
                bfr[ns][1] = __float_as_uint(sB[col * 36 + k0 + 4 + (lane & 3)]);
            }
#pragma unroll
            for (int ms = 0; ms < 2; ms++) {
                int row = wr * 32 + ms * 16 + (lane >> 2);
                unsigned a0 = __float_as_uint(sA[row * 36 + k0 + (lane & 3)]);
                unsigned a1 = __float_as_uint(sA[(row + 8) * 36 + k0 + (lane & 3)]);
                unsigned a2 = __float_as_uint(sA[row * 36 + k0 + 4 + (lane & 3)]);
                unsigned a3 = __float_as_uint(sA[(row + 8) * 36 + k0 + 4 + (lane & 3)]);
#pragma unroll
                for (int ns = 0; ns < NS; ns++)
                    mma8(acc[ms][ns], a0, a1, a2, a3, bfr[ns][0], bfr[ns][1]);
            }
        }
        __syncthreads();
    }

    if (MODE == 2) {
        dot += __shfl_xor_sync(0xffffffffu, dot, 1);
        if ((t & 1) == 0) dinv_s[t >> 1] = 1.0f / dot;
        __syncthreads();
    }

#pragma unroll
    for (int ms = 0; ms < 2; ms++) {
        int lr = wr * 32 + ms * 16 + (lane >> 2);
#pragma unroll
        for (int half = 0; half < 2; half++) {
            int row = n0 + lr + half * 8;
            if (row >= NNODES) continue;
            float sc = (MODE == 2) ? dinv_s[lr + half * 8] : 1.f;
#pragma unroll
            for (int ns = 0; ns < NS; ns++) {
                int col = o0 + wc * (BN / 2) + ns * 8 + (lane & 3) * 2;
                float v0 = acc[ms][ns][half * 2 + 0];
                float v1 = acc[ms][ns][half * 2 + 1];
                if (MODE == 1) {
                    v0 = (col < oreal) ? fmaxf(v0, 0.f) + EPSK : 0.f;
                    v1 = (col + 1 < oreal) ? fmaxf(v1, 0.f) + EPSK : 0.f;
                }
                if (MODE == 2) { v0 *= sc; v1 *= sc; }
                if (MODE == 3) { v0 += aux[col]; v1 += aux[col + 1]; }
                if (MODE != 3) { v0 = rtf(v0); v1 = rtf(v1); }
                *(float2*)&C[(size_t)row * ldc + col] = make_float2(v0, v1);
            }
        }
    }
}

// stage one 32-row slice of kf (128 m-cols, k-major) + v (64 d-cols) for tc_kv
__device__ __forceinline__ void stage_kv(float* sA, int head, int m0, int t, int nb)
{
    float* sB = sA + 32 * 136;
    unsigned ua = (unsigned)__cvta_generic_to_shared(sA);
    unsigned ub = (unsigned)__cvta_generic_to_shared(sB);
    const int hoff = head * MPAD;
#pragma unroll
    for (int i = 0; i < 4; i++) {
        int id = t + 256 * i, r = id >> 5, c4 = (id & 31) * 4, gn = nb + r;
        cpa16(ua + (r * 136 + c4) * 4, g_kf + (size_t)gn * ROWF + hoff + m0 + c4, gn < NNODES);
    }
#pragma unroll
    for (int i = 0; i < 2; i++) {
        int id = t + 256 * i, r = id >> 4, c4 = (id & 15) * 4, gn = nb + r;
        cpa16(ub + (r * 72 + c4) * 4, g_qkv + (size_t)gn * QKF + 384 + head * 64 + c4, gn < NNODES);
    }
}

// kv split-K: kvp[m][d] = sum_{n in chunk} kf[n][m]*v[n][d], ksum fused.
// sA layout: [row=n (0..31)][col=m (0..127)] stride 136 -> A-operand is k-major (col-major for mma).
__global__ __launch_bounds__(256) void tc_kv()
{
    extern __shared__ float sm[];
    constexpr int STK = 32 * 136 + 32 * 72;
    const int t = threadIdx.x, lane = t & 31, warp = t >> 5;
    const int wr = warp >> 1, wc = warp & 1;
    const int m0 = blockIdx.x * 128, chunk = blockIdx.y, head = blockIdx.z;
    const int nbase = chunk * CHN;

    float acc[2][4][4];
#pragma unroll
    for (int ms = 0; ms < 2; ms++)
#pragma unroll
        for (int ns = 0; ns < 4; ns++)
#pragma unroll
            for (int j = 0; j < 4; j++) acc[ms][ns][j] = 0.f;
    float sk[2][2] = {{0.f, 0.f}, {0.f, 0.f}};

    stage_kv(sm, head, m0, t, nbase);
    cp_commit();
    for (int it = 0; it < NKV; it++) {
        if (it + 1 < NKV) {
            stage_kv(sm + ((it + 1) & 1) * STK, head, m0, t, nbase + (it + 1) * 32);
            cp_commit(); cp_wait<1>();
        } else {
            cp_wait<0>();
        }
        __syncthreads();
        float* sA = sm + (it & 1) * STK; float* sB = sA + 32 * 136;
#pragma unroll
        for (int kk = 0; kk < 4; kk++) {
            int k0 = kk * 8;
            unsigned bfr[4][2];
#pragma unroll
            for (int ns = 0; ns < 4; ns++) {
                int col = wc * 32 + ns * 8 + (lane >> 2);
                bfr[ns][0] = __float_as_uint(sB[(k0 + (lane & 3)) * 72 + col]);
                bfr[ns][1] = __float_as_uint(sB[(k0 + 4 + (lane & 3)) * 72 + col]);
            }
#pragma unroll
            for (int ms = 0; ms < 2; ms++) {
                int mcol = wr * 32 + ms * 16 + (lane >> 2);
                float a0f = sA[(k0 + (lane & 3)) * 136 + mcol];
                float a1f = sA[(k0 + (lane & 3)) * 136 + mcol + 8];
                float a2f = sA[(k0 + 4 + (lane & 3)) * 136 + mcol];
                float a3f = sA[(k0 + 4 + (lane & 3)) * 136 + mcol + 8];
                if (wc == 0) { sk[ms][0] += a0f + a2f; sk[ms][1] += a1f + a3f; }
#pragma unroll
                for (int ns = 0; ns < 4; ns++)
                    mma8(acc[ms][ns], __float_as_uint(a0f), __float_as_uint(a1f),
                         __float_as_uint(a2f), __float_as_uint(a3f), bfr[ns][0], bfr[ns][1]);
            }
        }
        __syncthreads();
    }
#pragma unroll
    for (int ms = 0; ms < 2; ms++)
#pragma unroll
        for (int hh = 0; hh < 2; hh++) {
            float v = sk[ms][hh];
            v += __shfl_xor_sync(0xffffffffu, v, 1);
            v += __shfl_xor_sync(0xffffffffu, v, 2);
            if (wc == 0 && (lane & 3) == 0) {
                int m = m0 + wr * 32 + ms * 16 + (lane >> 2) + hh * 8;
                g_ksp[((size_t)head * NC + chunk) * 384 + m] = v;
            }
        }
    float* outp = g_kvp + ((size_t)head * NC + chunk) * 384 * 64;
#pragma unroll
    for (int ms = 0; ms < 2; ms++) {
        int mr = m0 + wr * 32 + ms * 16 + (lane >> 2);
#pragma unroll
        for (int ns = 0; ns < 4; ns++) {
            int col = wc * 32 + ns * 8 + (lane & 3) * 2;
            *(float2*)&outp[(size_t)mr * 64 + col] = make_float2(acc[ms][ns][0], acc[ms][ns][1]);
            *(float2*)&outp[(size_t)(mr + 8) * 64 + col] = make_float2(acc[ms][ns][2], acc[ms][ns][3]);
        }
    }
}

__global__ void kv_reduce2()
{
    int idx = blockIdx.x * blockDim.x + threadIdx.x;
    const int TOT = NHEAD * MPAD * 64;
    if (idx < TOT) {
        int head = idx / (MPAD * 64), rem = idx % (MPAD * 64);
        int m = rem >> 6, d = rem & 63;
        float s = 0.f;
        for (int c = 0; c < NC; c++)
            s += g_kvp[((size_t)head * NC + c) * 384 * 64 + m * 64 + d];
        g_kvT[(head * 64 + d) * MPAD + m] = rtf(s);
    } else if (idx < TOT + NHEAD * MPAD) {
        int r = idx - TOT, head = r / MPAD, m = r % MPAD;
        float s = 0.f;
        for (int c = 0; c < NC; c++)
            s += g_ksp[((size_t)head * NC + c) * 384 + m];
        g_ksum[head * MPAD + m] = s;
    }
}

__global__ void pack_weights(const float* __restrict__ Wq, const float* __restrict__ Wk,
                             const float* __restrict__ Wv, const float* __restrict__ Wo,
                             const float* __restrict__ proj)
{
    int idx = blockIdx.x * blockDim.x + threadIdx.x;
    const int S1 = NLAYER * QKF * FDIM, S2 = NLAYER * FDIM * FDIM, S3 = NLAYER * MPAD * HDIM;
    if (idx < S1) {
        int l = idx / (QKF * FDIM), r = idx % (QKF * FDIM);
        int row = r / FDIM, col = r % FDIM;
        const float* W = (row < 192) ? Wq : (row < 384) ? Wk : Wv;
        g_wqkv[idx] = rtf(W[((size_t)l * FDIM + row % 192) * FDIM + col]);
    } else if (idx < S1 + S2) {
        g_wor[idx - S1] = rtf(Wo[idx - S1]);
    } else if (idx < S1 + S2 + S3) {
        int j = idx - S1 - S2;
        int l = j / (MPAD * HDIM), r = j % (MPAD * HDIM);
        int row = r / HDIM, col = r % HDIM;
        g_projr[j] = (row < MRF) ? rtf(proj[((size_t)l * MRF + row) * HDIM + col]) : 0.f;
    }
}

__global__ void round_arr(const float* __restrict__ src, float* __restrict__ dst, int n4)
{
    int i = blockIdx.x * blockDim.x + threadIdx.x;
    if (i < n4) {
        float4 v = ((const float4*)src)[i];
        v.x = rtf(v.x); v.y = rtf(v.y); v.z = rtf(v.z); v.w = rtf(v.w);
        ((float4*)dst)[i] = v;
    }
}

__global__ void ln_kernel(const float* __restrict__ in, float* __restrict__ out,
                          const float* __restrict__ gamma, const float* __restrict__ beta,
                          int relu_round)
{
    int node = blockIdx.x * (blockDim.x >> 5) + (threadIdx.x >> 5);
    int lane = threadIdx.x & 31;
    if (node >= NNODES) return;
    const float* row = in + (size_t)node * FDIM;
    float x[6], s = 0.f;
#pragma unroll
    for (int i = 0; i < 6; i++) { x[i] = row[lane + 32 * i]; s += x[i]; }
#pragma unroll
    for (int o = 16; o; o >>= 1) s += __shfl_xor_sync(0xffffffffu, s, o);
    float mu = s * (1.0f / FDIM), v = 0.f;
#pragma unroll
    for (int i = 0; i < 6; i++) { float d = x[i] - mu; v += d * d; }
#pragma unroll
    for (int o = 16; o; o >>= 1) v += __shfl_xor_sync(0xffffffffu, v, o);
    float inv = rsqrtf(v * (1.0f / FDIM) + LNEPS);
    float* orow = out + (size_t)node * FDIM;
#pragma unroll
    for (int i = 0; i < 6; i++) {
        int o = lane + 32 * i;
        float y = (x[i] - mu) * inv * gamma[o] + beta[o];
        if (relu_round) y = rtf(fmaxf(y, 0.f));
        orow[o] = y;
    }
}

extern "C" void kernel_launch(void* const* d_in, const int* in_sizes, int n_in,
                              void* d_out, int out_size)
{
    const float* h0    = (const float*)d_in[0];
    const float* eattr = (const float*)d_in[1];
    const float* Wq = (const float*)d_in[3];
    const float* Wk = (const float*)d_in[4];
    const float* Wv = (const float*)d_in[5];
    const float* Wo = (const float*)d_in[6];
    const float* bo = (const float*)d_in[7];
    const float* ga = (const float*)d_in[8];
    const float* be = (const float*)d_in[9];
    const float* pr = (const float*)d_in[10];
    float* out = (float*)d_out;

    float *qkv, *qf, *kf, *attn, *tmp, *hbuf, *kvT, *ksum, *wqkv, *wor, *projr;
    cudaGetSymbolAddress((void**)&qkv, g_qkv);
    cudaGetSymbolAddress((void**)&qf, g_qf);
    cudaGetSymbolAddress((void**)&kf, g_kf);
    cudaGetSymbolAddress((void**)&attn, g_attn);
    cudaGetSymbolAddress((void**)&tmp, g_tmp);
    cudaGetSymbolAddress((void**)&hbuf, g_h);
    cudaGetSymbolAddress((void**)&kvT, g_kvT);
    cudaGetSymbolAddress((void**)&ksum, g_ksum);
    cudaGetSymbolAddress((void**)&wqkv, g_wqkv);
    cudaGetSymbolAddress((void**)&wor, g_wor);
    cudaGetSymbolAddress((void**)&projr, g_projr);

    const int smem64 = ((128 + 64) * 36 * 2 + 448) * 4;
    const int smem96 = ((128 + 96) * 36 * 2 + 448) * 4;
    const int smemkv = (32 * 136 + 32 * 72) * 2 * 4;
    cudaFuncSetAttribute(tc_gemm2<0, 64>, cudaFuncAttributeMaxDynamicSharedMemorySize, smem64);
    cudaFuncSetAttribute(tc_gemm2<1, 96>, cudaFuncAttributeMaxDynamicSharedMemorySize, smem96);
    cudaFuncSetAttribute(tc_gemm2<2, 64>, cudaFuncAttributeMaxDynamicSharedMemorySize, smem64);
    cudaFuncSetAttribute(tc_gemm2<3, 64>, cudaFuncAttributeMaxDynamicSharedMemorySize, smem64);
    cudaFuncSetAttribute(tc_kv, cudaFuncAttributeMaxDynamicSharedMemorySize, smemkv);

    cudaMemcpyAsync(out + (size_t)NNODES * FDIM, eattr,
                    (size_t)EEDGE * 8 * sizeof(float), cudaMemcpyDeviceToDevice);

    const int PACKN = NLAYER * (QKF * FDIM + FDIM * FDIM + MPAD * HDIM);
    pack_weights<<<(PACKN + 255) / 256, 256>>>(Wq, Wk, Wv, Wo, pr);
    round_arr<<<(NNODES * FDIM / 4 + 255) / 256, 256>>>(h0, hbuf, NNODES * FDIM / 4);

    for (int l = 0; l < NLAYER; l++) {
        float* hout = (l == NLAYER - 1) ? out : hbuf;
        // QKV (packed B = [Wq;Wk;Wv])
        tc_gemm2<0, 64><<<dim3(9, NB128, 1), 256, smem64>>>(
            hbuf, FDIM, wqkv + (size_t)l * QKF * FDIM, FDIM, QKF,
            qkv, QKF, FDIM, 0, nullptr, 0, 0);
        // feature maps (blockIdx.z = head)
        tc_gemm2<1, 96><<<dim3(3, NB128, 3), 256, smem96>>>(
            qkv, QKF, projr + (size_t)l * MPAD * HDIM, HDIM, MPAD,
            qf, ROWF, HDIM, MRF, nullptr, 64, MPAD);
        tc_gemm2<1, 96><<<dim3(3, NB128, 3), 256, smem96>>>(
            qkv + 192, QKF, projr + (size_t)l * MPAD * HDIM, HDIM, MPAD,
            kf, ROWF, HDIM, MRF, nullptr, 64, MPAD);
        // kv + fused ksum (split-K), deterministic reduce
        tc_kv<<<dim3(3, NC, 3), 256, smemkv>>>();
        kv_reduce2<<<(NHEAD * MPAD * 65 + 255) / 256, 256>>>();
        // out = (qf @ kvT^T) * 1/(qf . ksum)   (blockIdx.z = head)
        tc_gemm2<2, 64><<<dim3(1, NB128, 3), 256, smem64>>>(
            qf, ROWF, kvT, MPAD, HDIM,
            attn, FDIM, MPAD, 0, ksum, MPAD, 64);
        // Wo + bias
        tc_gemm2<3, 64><<<dim3(3, NB128, 1), 256, smem64>>>(
            attn, FDIM, wor + (size_t)l * FDIM * FDIM, FDIM, FDIM,
            tmp, FDIM, FDIM, 0, bo + l * FDIM, 0, 0);
        // LayerNorm (+relu+round for intermediate layers)
        ln_kernel<<<(NNODES + 3) / 4, 128>>>(tmp, hout, ga + l * FDIM, be + l * FDIM,
                                             (l < NLAYER - 1) ? 1 : 0);
    }
}

// round 7
// speedup vs baseline: 3.8856x; 1.1922x over previous
#include <cuda_runtime.h>
#include <cstdint>

#define NNODES 100000
#define FDIM 192
#define NHEAD 3
#define HDIM 64
#define MRF 266
#define MPAD 288
#define QKF 576
#define NLAYER 4
#define EEDGE 1000000
#define EPSK 1e-3f
#define LNEPS 1e-5f
#define CHN 1056
#define NC 96
#define NKV (CHN / 32)
#define NB128 ((NNODES + 127) / 128)

__device__ float g_qkv[(size_t)NNODES * QKF];
__device__ float g_attn[(size_t)NNODES * FDIM];
__device__ float g_tmp[(size_t)NNODES * FDIM];
__device__ float g_h[(size_t)NNODES * FDIM];
__device__ float g_kvp[(size_t)NHEAD * NC * MPAD * 64];
__device__ float g_ksp[(size_t)NHEAD * NC * MPAD];
__device__ float g_kvT[NHEAD * 64 * MPAD];
__device__ float g_ksum[NHEAD * MPAD];
__device__ float g_wqkv[NLAYER * QKF * FDIM];
__device__ float g_wor[NLAYER * FDIM * FDIM];
__device__ float g_projr[NLAYER * MPAD * HDIM];

__device__ __forceinline__ float rtf(float x) {
    unsigned u; asm("cvt.rna.tf32.f32 %0, %1;" : "=r"(u) : "f"(x));
    return __uint_as_float(u);
}
__device__ __forceinline__ void cpa16(unsigned dst, const float* src, bool p) {
    int sz = p ? 16 : 0;
    asm volatile("cp.async.cg.shared.global [%0], [%1], 16, %2;" :: "r"(dst), "l"(src), "r"(sz));
}
__device__ __forceinline__ void cp_commit() { asm volatile("cp.async.commit_group;"); }
template <int N> __device__ __forceinline__ void cp_wait() {
    asm volatile("cp.async.wait_group %0;" :: "n"(N));
}
__device__ __forceinline__ void mma8(float* c, unsigned a0, unsigned a1, unsigned a2,
                                     unsigned a3, unsigned b0, unsigned b1) {
    asm volatile("mma.sync.aligned.m16n8k8.row.col.f32.tf32.tf32.f32 "
                 "{%0,%1,%2,%3}, {%4,%5,%6,%7}, {%8,%9}, {%0,%1,%2,%3};"
                 : "+f"(c[0]), "+f"(c[1]), "+f"(c[2]), "+f"(c[3])
                 : "r"(a0), "r"(a1), "r"(a2), "r"(a3), "r"(b0), "r"(b1));
}

// ======================= generic GEMM (QKV / Wo) =======================
template <int BN>
__device__ __forceinline__ void stage_gemm(float* sA, const float* A, int lda,
                                           const float* B, int ldb, int brows,
                                           int n0, int o0, int t, int kb)
{
    float* sB = sA + 128 * 36;
    unsigned ua = (unsigned)__cvta_generic_to_shared(sA);
    unsigned ub = (unsigned)__cvta_generic_to_shared(sB);
#pragma unroll
    for (int i = 0; i < 4; i++) {
        int id = t + 256 * i, r = id >> 3, c4 = (id & 7) * 4;
        cpa16(ua + (r * 36 + c4) * 4, A + (size_t)(n0 + r) * lda + kb + c4, (n0 + r) < NNODES);
    }
#pragma unroll
    for (int i = 0; i < BN / 32; i++) {
        int id = t + 256 * i, r = id >> 3, c4 = (id & 7) * 4;
        cpa16(ub + (r * 36 + c4) * 4, B + (size_t)(o0 + r) * ldb + kb + c4, (o0 + r) < brows);
    }
}

// MODE 0: round-store (QKV)   MODE 3: +bias (Wo)
template <int MODE, int BN>
__global__ __launch_bounds__(256) void tc_gemm2(
    const float* __restrict__ A, int lda,
    const float* __restrict__ B, int ldb, int brows,
    float* __restrict__ C, int ldc,
    int K, const float* __restrict__ aux)
{
    extern __shared__ float sm[];
    constexpr int STG = (128 + BN) * 36;
    constexpr int NS = BN / 16;
    const int t = threadIdx.x, lane = t & 31, warp = t >> 5;
    const int wr = warp >> 1, wc = warp & 1;
    const int n0 = blockIdx.y * 128, o0 = blockIdx.x * BN;

    float acc[2][NS][4];
#pragma unroll
    for (int ms = 0; ms < 2; ms++)
#pragma unroll
        for (int ns = 0; ns < NS; ns++)
#pragma unroll
            for (int j = 0; j < 4; j++) acc[ms][ns][j] = 0.f;

    const int NK = K >> 5;
    stage_gemm<BN>(sm, A, lda, B, ldb, brows, n0, o0, t, 0);
    cp_commit();
    for (int it = 0; it < NK; it++) {
        if (it + 1 < NK) {
            stage_gemm<BN>(sm + ((it + 1) & 1) * STG, A, lda, B, ldb, brows,
                           n0, o0, t, (it + 1) << 5);
            cp_commit(); cp_wait<1>();
        } else {
            cp_wait<0>();
        }
        __syncthreads();
        float* sA = sm + (it & 1) * STG; float* sB = sA + 128 * 36;
#pragma unroll
        for (int kk = 0; kk < 4; kk++) {
            int k0 = kk * 8;
            unsigned bf0[NS], bf1[NS];
#pragma unroll
            for (int ns = 0; ns < NS; ns++) {
                int col = wc * (BN / 2) + ns * 8 + (lane >> 2);
                bf0[ns] = __float_as_uint(sB[col * 36 + k0 + (lane & 3)]);
                bf1[ns] = __float_as_uint(sB[col * 36 + k0 + 4 + (lane & 3)]);
            }
#pragma unroll
            for (int ms = 0; ms < 2; ms++) {
                int row = wr * 32 + ms * 16 + (lane >> 2);
                unsigned a0 = __float_as_uint(sA[row * 36 + k0 + (lane & 3)]);
                unsigned a1 = __float_as_uint(sA[(row + 8) * 36 + k0 + (lane & 3)]);
                unsigned a2 = __float_as_uint(sA[row * 36 + k0 + 4 + (lane & 3)]);
                unsigned a3 = __float_as_uint(sA[(row + 8) * 36 + k0 + 4 + (lane & 3)]);
#pragma unroll
                for (int ns = 0; ns < NS; ns++)
                    mma8(acc[ms][ns], a0, a1, a2, a3, bf0[ns], bf1[ns]);
            }
        }
        __syncthreads();
    }

#pragma unroll
    for (int ms = 0; ms < 2; ms++) {
        int lr = wr * 32 + ms * 16 + (lane >> 2);
#pragma unroll
        for (int half = 0; half < 2; half++) {
            int row = n0 + lr + half * 8;
            if (row >= NNODES) continue;
#pragma unroll
            for (int ns = 0; ns < NS; ns++) {
                int col = o0 + wc * (BN / 2) + ns * 8 + (lane & 3) * 2;
                float v0 = acc[ms][ns][half * 2 + 0];
                float v1 = acc[ms][ns][half * 2 + 1];
                if (MODE == 3) { v0 += aux[col]; v1 += aux[col + 1]; }
                else { v0 = rtf(v0); v1 = rtf(v1); }
                *(float2*)&C[(size_t)row * ldc + col] = make_float2(v0, v1);
            }
        }
    }
}

// ======================= fused kf-feature + kv split-K =======================
// per (m-block 96, chunk, head): F = relu(k@projT)+eps (rounded), then
// kvp[m][d] += F^T @ v over 32-node steps; ksum fused.
__global__ __launch_bounds__(256) void tc_kvf(const float* __restrict__ proj)
{
    extern __shared__ float sm[];
    float* sPj = sm;                    // 96*68
    float* sK  = sPj + 96 * 68;         // 2 * 32*68
    float* sV  = sK + 2 * 32 * 68;      // 2 * 32*72
    float* sF  = sV + 2 * 32 * 72;      // 32*104

    const int t = threadIdx.x, lane = t & 31, warp = t >> 5;
    const int fwr = warp & 1, fwc = warp >> 1;   // feature map: 2x4
    const int mw = warp & 1, dw = warp >> 1;     // main map: 2x4
    const int m0 = blockIdx.x * 96, chunk = blockIdx.y, head = blockIdx.z;
    const int nbase = chunk * CHN;

    // proj block (static) + first k/v stage in group 0
    {
        unsigned up = (unsigned)__cvta_generic_to_shared(sPj);
#pragma unroll
        for (int i = 0; i < 6; i++) {
            int id = t + 256 * i, r = id >> 4, c4 = (id & 15) * 4;
            cpa16(up + (r * 68 + c4) * 4, proj + (size_t)(m0 + r) * HDIM + c4, true);
        }
        unsigned uk = (unsigned)__cvta_generic_to_shared(sK);
        unsigned uv = (unsigned)__cvta_generic_to_shared(sV);
#pragma unroll
        for (int i = 0; i < 2; i++) {
            int id = t + 256 * i, r = id >> 4, c4 = (id & 15) * 4, gn = nbase + r;
            cpa16(uk + (r * 68 + c4) * 4, g_qkv + (size_t)gn * QKF + 192 + head * 64 + c4, gn < NNODES);
            cpa16(uv + (r * 72 + c4) * 4, g_qkv + (size_t)gn * QKF + 384 + head * 64 + c4, gn < NNODES);
        }
        cp_commit();
    }

    float acc[3][2][4];
#pragma unroll
    for (int ms = 0; ms < 3; ms++)
#pragma unroll
        for (int ns = 0; ns < 2; ns++)
#pragma unroll
            for (int j = 0; j < 4; j++) acc[ms][ns][j] = 0.f;
    float facc[3][4];
#pragma unroll
    for (int ns = 0; ns < 3; ns++)
#pragma unroll
        for (int j = 0; j < 4; j++) facc[ns][j] = 0.f;
    float sk[3][2] = {{0.f,0.f},{0.f,0.f},{0.f,0.f}};

    for (int it = 0; it < NKV; it++) {
        if (it + 1 < NKV) {
            int b = (it + 1) & 1, nb = nbase + (it + 1) * 32;
            unsigned uk = (unsigned)__cvta_generic_to_shared(sK + b * 32 * 68);
            unsigned uv = (unsigned)__cvta_generic_to_shared(sV + b * 32 * 72);
#pragma unroll
            for (int i = 0; i < 2; i++) {
                int id = t + 256 * i, r = id >> 4, c4 = (id & 15) * 4, gn = nb + r;
                cpa16(uk + (r * 68 + c4) * 4, g_qkv + (size_t)gn * QKF + 192 + head * 64 + c4, gn < NNODES);
                cpa16(uv + (r * 72 + c4) * 4, g_qkv + (size_t)gn * QKF + 384 + head * 64 + c4, gn < NNODES);
            }
            cp_commit(); cp_wait<1>();
        } else {
            cp_wait<0>();
        }
        __syncthreads();
        float* cK = sK + (it & 1) * 32 * 68;
        float* cV = sV + (it & 1) * 32 * 72;

        // feature mma: F(32 n x 96 m) = k_tile(32x64) @ projT
#pragma unroll
        for (int kk = 0; kk < 8; kk++) {
            int k0 = kk * 8;
            int row = fwr * 16 + (lane >> 2);
            unsigned a0 = __float_as_uint(cK[row * 68 + k0 + (lane & 3)]);
            unsigned a1 = __float_as_uint(cK[(row + 8) * 68 + k0 + (lane & 3)]);
            unsigned a2 = __float_as_uint(cK[row * 68 + k0 + 4 + (lane & 3)]);
            unsigned a3 = __float_as_uint(cK[(row + 8) * 68 + k0 + 4 + (lane & 3)]);
#pragma unroll
            for (int ns = 0; ns < 3; ns++) {
                int colm = fwc * 24 + ns * 8 + (lane >> 2);
                unsigned b0 = __float_as_uint(sPj[colm * 68 + k0 + (lane & 3)]);
                unsigned b1 = __float_as_uint(sPj[colm * 68 + k0 + 4 + (lane & 3)]);
                mma8(facc[ns], a0, a1, a2, a3, b0, b1);
            }
        }
        // relu/eps/round, zero invalid nodes & padded m, store F [n][m] stride 104
        {
            int rown = fwr * 16 + (lane >> 2);
            int gn0 = nbase + it * 32 + rown, gn1 = gn0 + 8;
#pragma unroll
            for (int ns = 0; ns < 3; ns++) {
                int colm = fwc * 24 + ns * 8 + (lane & 3) * 2;
                int gm = m0 + colm;
                float v0 = (gn0 < NNODES && gm < MRF)     ? rtf(fmaxf(facc[ns][0], 0.f) + EPSK) : 0.f;
                float v1 = (gn0 < NNODES && gm + 1 < MRF) ? rtf(fmaxf(facc[ns][1], 0.f) + EPSK) : 0.f;
                float v2 = (gn1 < NNODES && gm < MRF)     ? rtf(fmaxf(facc[ns][2], 0.f) + EPSK) : 0.f;
                float v3 = (gn1 < NNODES && gm + 1 < MRF) ? rtf(fmaxf(facc[ns][3], 0.f) + EPSK) : 0.f;
                *(float2*)&sF[rown * 104 + colm] = make_float2(v0, v1);
                *(float2*)&sF[(rown + 8) * 104 + colm] = make_float2(v2, v3);
                facc[ns][0] = facc[ns][1] = facc[ns][2] = facc[ns][3] = 0.f;
            }
        }
        __syncthreads();
        // main mma: kv(96 m x 64 d) += F^T(96x32) @ v(32x64); ksum from A-frags
#pragma unroll
        for (int kk = 0; kk < 4; kk++) {
            int k0 = kk * 8;
            unsigned bf0[2], bf1[2];
#pragma unroll
            for (int ns = 0; ns < 2; ns++) {
                int cold = dw * 16 + ns * 8 + (lane >> 2);
                bf0[ns] = __float_as_uint(cV[(k0 + (lane & 3)) * 72 + cold]);
                bf1[ns] = __float_as_uint(cV[(k0 + 4 + (lane & 3)) * 72 + cold]);
            }
#pragma unroll
            for (int ms = 0; ms < 3; ms++) {
                int mcol = mw * 48 + ms * 16 + (lane >> 2);
                float a0f = sF[(k0 + (lane & 3)) * 104 + mcol];
                float a1f = sF[(k0 + (lane & 3)) * 104 + mcol + 8];
                float a2f = sF[(k0 + 4 + (lane & 3)) * 104 + mcol];
                float a3f = sF[(k0 + 4 + (lane & 3)) * 104 + mcol + 8];
                if (dw == 0) { sk[ms][0] += a0f + a2f; sk[ms][1] += a1f + a3f; }
#pragma unroll
                for (int ns = 0; ns < 2; ns++)
                    mma8(acc[ms][ns], __float_as_uint(a0f), __float_as_uint(a1f),
                         __float_as_uint(a2f), __float_as_uint(a3f), bf0[ns], bf1[ns]);
            }
        }
        __syncthreads();
    }

    // ksum partials
#pragma unroll
    for (int ms = 0; ms < 3; ms++)
#pragma unroll
        for (int hh = 0; hh < 2; hh++) {
            float v = sk[ms][hh];
            v += __shfl_xor_sync(0xffffffffu, v, 1);
            v += __shfl_xor_sync(0xffffffffu, v, 2);
            if (dw == 0 && (lane & 3) == 0) {
                int m = m0 + mw * 48 + ms * 16 + (lane >> 2) + hh * 8;
                g_ksp[((size_t)head * NC + chunk) * MPAD + m] = v;
            }
        }
    // kv partials
    float* outp = g_kvp + ((size_t)head * NC + chunk) * MPAD * 64;
#pragma unroll
    for (int ms = 0; ms < 3; ms++) {
        int mr = m0 + mw * 48 + ms * 16 + (lane >> 2);
#pragma unroll
        for (int ns = 0; ns < 2; ns++) {
            int col = dw * 16 + ns * 8 + (lane & 3) * 2;
            *(float2*)&outp[(size_t)mr * 64 + col] = make_float2(acc[ms][ns][0], acc[ms][ns][1]);
            *(float2*)&outp[(size_t)(mr + 8) * 64 + col] = make_float2(acc[ms][ns][2], acc[ms][ns][3]);
        }
    }
}

__global__ void kv_reduce2()
{
    int idx = blockIdx.x * blockDim.x + threadIdx.x;
    const int TOT = NHEAD * MPAD * 64;
    if (idx < TOT) {
        int head = idx / (MPAD * 64), rem = idx % (MPAD * 64);
        int m = rem >> 6, d = rem & 63;
        float s = 0.f;
        for (int c = 0; c < NC; c++)
            s += g_kvp[((size_t)(head * NC + c) * MPAD + m) * 64 + d];
        g_kvT[(head * 64 + d) * MPAD + m] = rtf(s);
    } else if (idx < TOT + NHEAD * MPAD) {
        int r = idx - TOT, head = r / MPAD, m = r % MPAD;
        float s = 0.f;
        for (int c = 0; c < NC; c++)
            s += g_ksp[(size_t)(head * NC + c) * MPAD + m];
        g_ksum[head * MPAD + m] = s;
    }
}

// ======================= fused qf-feature + FAVOR+ out-GEMM =======================
// per (128-node tile, head): q resident in smem; 9 slices of 32 m:
// F = relu(q@projT)+eps (rounded) -> out += F @ kvT_slice^T, dot += F . ksum_slice
__global__ __launch_bounds__(256) void tc_attn(const float* __restrict__ proj)
{
    extern __shared__ float sm[];
    float* sQ = sm;                       // 128*68
    float* sF = sQ + 128 * 68;            // 2 * 128*36
    float* sP = sF + 2 * 128 * 36;        // 2 * 32*68
    float* sKV = sP + 2 * 32 * 68;        // 2 * 64*36
    float* sKS = sKV + 2 * 64 * 36;       // 288
    float* sDinv = sKS + MPAD;            // 128

    const int t = threadIdx.x, lane = t & 31, warp = t >> 5;
    const int wr = warp >> 1, wc = warp & 1;
    const int n0 = blockIdx.x * 128, head = blockIdx.y;

    {
        unsigned ua = (unsigned)__cvta_generic_to_shared(sQ);
#pragma unroll
        for (int i = 0; i < 8; i++) {
            int id = t + 256 * i, r = id >> 4, c4 = (id & 15) * 4;
            cpa16(ua + (r * 68 + c4) * 4, g_qkv + (size_t)(n0 + r) * QKF + head * 64 + c4,
                  (n0 + r) < NNODES);
        }
        unsigned up = (unsigned)__cvta_generic_to_shared(sP);
        unsigned uk = (unsigned)__cvta_generic_to_shared(sKV);
#pragma unroll
        for (int i = 0; i < 2; i++) {
            int id = t + 256 * i, r = id >> 4, c4 = (id & 15) * 4;
            cpa16(up + (r * 68 + c4) * 4, proj + (size_t)r * HDIM + c4, true);
        }
#pragma unroll
        for (int i = 0; i < 2; i++) {
            int id = t + 256 * i, r = id >> 3, c4 = (id & 7) * 4;
            cpa16(uk + (r * 36 + c4) * 4, g_kvT + (size_t)(head * 64 + r) * MPAD + c4, true);
        }
        cp_commit();
    }
    for (int i = t; i < MPAD; i += 256) sKS[i] = g_ksum[head * MPAD + i];

    float acc[2][4][4];
#pragma unroll
    for (int ms = 0; ms < 2; ms++)
#pragma unroll
        for (int ns = 0; ns < 4; ns++)
#pragma unroll
            for (int j = 0; j < 4; j++) acc[ms][ns][j] = 0.f;
    float facc[2][2][4];
#pragma unroll
    for (int ms = 0; ms < 2; ms++)
#pragma unroll
        for (int ns = 0; ns < 2; ns++)
#pragma unroll
            for (int j = 0; j < 4; j++) facc[ms][ns][j] = 0.f;
    float dot = 0.f;

    for (int s = 0; s < 9; s++) {
        if (s < 8) {
            int b = (s + 1) & 1;
            unsigned up = (unsigned)__cvta_generic_to_shared(sP + b * 32 * 68);
            unsigned uk = (unsigned)__cvta_generic_to_shared(sKV + b * 64 * 36);
#pragma unroll
            for (int i = 0; i < 2; i++) {
                int id = t + 256 * i, r = id >> 4, c4 = (id & 15) * 4;
                cpa16(up + (r * 68 + c4) * 4, proj + (size_t)((s + 1) * 32 + r) * HDIM + c4, true);
            }
#pragma unroll
            for (int i = 0; i < 2; i++) {
                int id = t + 256 * i, r = id >> 3, c4 = (id & 7) * 4;
                cpa16(uk + (r * 36 + c4) * 4,
                      g_kvT + (size_t)(head * 64 + r) * MPAD + (s + 1) * 32 + c4, true);
            }
            cp_commit(); cp_wait<1>();
        } else {
            cp_wait<0>();
        }
        __syncthreads();
        float* cP = sP + (s & 1) * 32 * 68;
        float* cKV = sKV + (s & 1) * 64 * 36;
        float* cF = sF + (s & 1) * 128 * 36;

        // feature mma: F(128 x 32) = q(128x64) @ proj_sliceT
#pragma unroll
        for (int kk = 0; kk < 8; kk++) {
            int k0 = kk * 8;
            unsigned bf0[2], bf1[2];
#pragma unroll
            for (int ns = 0; ns < 2; ns++) {
                int col = wc * 16 + ns * 8 + (lane >> 2);
                bf0[ns] = __float_as_uint(cP[col * 68 + k0 + (lane & 3)]);
                bf1[ns] = __float_as_uint(cP[col * 68 + k0 + 4 + (lane & 3)]);
            }
#pragma unroll
            for (int ms = 0; ms < 2; ms++) {
                int row = wr * 32 + ms * 16 + (lane >> 2);
                unsigned a0 = __float_as_uint(sQ[row * 68 + k0 + (lane & 3)]);
                unsigned a1 = __float_as_uint(sQ[(row + 8) * 68 + k0 + (lane & 3)]);
                unsigned a2 = __float_as_uint(sQ[row * 68 + k0 + 4 + (lane & 3)]);
                unsigned a3 = __float_as_uint(sQ[(row + 8) * 68 + k0 + 4 + (lane & 3)]);
#pragma unroll
                for (int ns = 0; ns < 2; ns++)
                    mma8(facc[ms][ns], a0, a1, a2, a3, bf0[ns], bf1[ns]);
            }
        }
        // relu/eps/round, store F
#pragma unroll
        for (int ms = 0; ms < 2; ms++) {
            int row = wr * 32 + ms * 16 + (lane >> 2);
#pragma unroll
            for (int ns = 0; ns < 2; ns++) {
                int colL = wc * 16 + ns * 8 + (lane & 3) * 2;
                int gm = s * 32 + colL;
                float v0 = (gm < MRF)     ? rtf(fmaxf(facc[ms][ns][0], 0.f) + EPSK) : 0.f;
                float v1 = (gm + 1 < MRF) ? rtf(fmaxf(facc[ms][ns][1], 0.f) + EPSK) : 0.f;
                float v2 = (gm < MRF)     ? rtf(fmaxf(facc[ms][ns][2], 0.f) + EPSK) : 0.f;
                float v3 = (gm + 1 < MRF) ? rtf(fmaxf(facc[ms][ns][3], 0.f) + EPSK) : 0.f;
                *(float2*)&cF[row * 36 + colL] = make_float2(v0, v1);
                *(float2*)&cF[(row + 8) * 36 + colL] = make_float2(v2, v3);
                facc[ms][ns][0] = facc[ms][ns][1] = facc[ms][ns][2] = facc[ms][ns][3] = 0.f;
            }
        }
        __syncthreads();
        // denominator partial
        {
            int rr = t >> 1, kh = (t & 1) * 16;
#pragma unroll
            for (int j = 0; j < 4; j++) {
                float4 fv = *(const float4*)&cF[rr * 36 + kh + j * 4];
                float4 kv = *(const float4*)&sKS[s * 32 + kh + j * 4];
                dot += fv.x * kv.x + fv.y * kv.y + fv.z * kv.z + fv.w * kv.w;
            }
        }
        // main mma: out(128 x 64) += F(128x32) @ kvT_slice^T
#pragma unroll
        for (int kk = 0; kk < 4; kk++) {
            int k0 = kk * 8;
            unsigned bf0[4], bf1[4];
#pragma unroll
            for (int ns = 0; ns < 4; ns++) {
                int col = wc * 32 + ns * 8 + (lane >> 2);
                bf0[ns] = __float_as_uint(cKV[col * 36 + k0 + (lane & 3)]);
                bf1[ns] = __float_as_uint(cKV[col * 36 + k0 + 4 + (lane & 3)]);
            }
#pragma unroll
            for (int ms = 0; ms < 2; ms++) {
                int row = wr * 32 + ms * 16 + (lane >> 2);
                unsigned a0 = __float_as_uint(cF[row * 36 + k0 + (lane & 3)]);
                unsigned a1 = __float_as_uint(cF[(row + 8) * 36 + k0 + (lane & 3)]);
                unsigned a2 = __float_as_uint(cF[row * 36 + k0 + 4 + (lane & 3)]);
                unsigned a3 = __float_as_uint(cF[(row + 8) * 36 + k0 + 4 + (lane & 3)]);
#pragma unroll
                for (int ns = 0; ns < 4; ns++)
                    mma8(acc[ms][ns], a0, a1, a2, a3, bf0[ns], bf1[ns]);
            }
        }
        __syncthreads();
    }

    dot += __shfl_xor_sync(0xffffffffu, dot, 1);
    if ((t & 1) == 0) sDinv[t >> 1] = 1.0f / dot;
    __syncthreads();

#pragma unroll
    for (int ms = 0; ms < 2; ms++) {
        int lr = wr * 32 + ms * 16 + (lane >> 2);
#pragma unroll
        for (int half = 0; half < 2; half++) {
            int row = n0 + lr + half * 8;
            if (row >= NNODES) continue;
            float sc = sDinv[lr + half * 8];
#pragma unroll
            for (int ns = 0; ns < 4; ns++) {
                int col = wc * 32 + ns * 8 + (lane & 3) * 2;
                float v0 = rtf(acc[ms][ns][half * 2 + 0] * sc);
                float v1 = rtf(acc[ms][ns][half * 2 + 1] * sc);
                *(float2*)&g_attn[(size_t)row * FDIM + head * 64 + col] = make_float2(v0, v1);
            }
        }
    }
}

// ======================= misc =======================
__global__ void pack_weights(const float* __restrict__ Wq, const float* __restrict__ Wk,
                             const float* __restrict__ Wv, const float* __restrict__ Wo,
                             const float* __restrict__ proj)
{
    int idx = blockIdx.x * blockDim.x + threadIdx.x;
    const int S1 = NLAYER * QKF * FDIM, S2 = NLAYER * FDIM * FDIM, S3 = NLAYER * MPAD * HDIM;
    if (idx < S1) {
        int l = idx / (QKF * FDIM), r = idx % (QKF * FDIM);
        int row = r / FDIM, col = r % FDIM;
        const float* W = (row < 192) ? Wq : (row < 384) ? Wk : Wv;
        g_wqkv[idx] = rtf(W[((size_t)l * FDIM + row % 192) * FDIM + col]);
    } else if (idx < S1 + S2) {
        g_wor[idx - S1] = rtf(Wo[idx - S1]);
    } else if (idx < S1 + S2 + S3) {
        int j = idx - S1 - S2;
        int l = j / (MPAD * HDIM), r = j % (MPAD * HDIM);
        int row = r / HDIM, col = r % HDIM;
        g_projr[j] = (row < MRF) ? rtf(proj[((size_t)l * MRF + row) * HDIM + col]) : 0.f;
    }
}

__global__ void round_arr(const float* __restrict__ src, float* __restrict__ dst, int n4)
{
    int i = blockIdx.x * blockDim.x + threadIdx.x;
    if (i < n4) {
        float4 v = ((const float4*)src)[i];
        v.x = rtf(v.x); v.y = rtf(v.y); v.z = rtf(v.z); v.w = rtf(v.w);
        ((float4*)dst)[i] = v;
    }
}

__global__ void ln_kernel(const float* __restrict__ in, float* __restrict__ out,
                          const float* __restrict__ gamma, const float* __restrict__ beta,
                          int relu_round)
{
    int node = blockIdx.x * (blockDim.x >> 5) + (threadIdx.x >> 5);
    int lane = threadIdx.x & 31;
    if (node >= NNODES) return;
    const float* row = in + (size_t)node * FDIM;
    float x[6], s = 0.f;
#pragma unroll
    for (int i = 0; i < 6; i++) { x[i] = row[lane + 32 * i]; s += x[i]; }
#pragma unroll
    for (int o = 16; o; o >>= 1) s += __shfl_xor_sync(0xffffffffu, s, o);
    float mu = s * (1.0f / FDIM), v = 0.f;
#pragma unroll
    for (int i = 0; i < 6; i++) { float d = x[i] - mu; v += d * d; }
#pragma unroll
    for (int o = 16; o; o >>= 1) v += __shfl_xor_sync(0xffffffffu, v, o);
    float inv = rsqrtf(v * (1.0f / FDIM) + LNEPS);
    float* orow = out + (size_t)node * FDIM;
#pragma unroll
    for (int i = 0; i < 6; i++) {
        int o = lane + 32 * i;
        float y = (x[i] - mu) * inv * gamma[o] + beta[o];
        if (relu_round) y = rtf(fmaxf(y, 0.f));
        orow[o] = y;
    }
}

extern "C" void kernel_launch(void* const* d_in, const int* in_sizes, int n_in,
                              void* d_out, int out_size)
{
    const float* h0    = (const float*)d_in[0];
    const float* eattr = (const float*)d_in[1];
    const float* Wq = (const float*)d_in[3];
    const float* Wk = (const float*)d_in[4];
    const float* Wv = (const float*)d_in[5];
    const float* Wo = (const float*)d_in[6];
    const float* bo = (const float*)d_in[7];
    const float* ga = (const float*)d_in[8];
    const float* be = (const float*)d_in[9];
    const float* pr = (const float*)d_in[10];
    float* out = (float*)d_out;

    float *qkv, *attn, *tmp, *hbuf, *wqkv, *wor, *projr;
    cudaGetSymbolAddress((void**)&qkv, g_qkv);
    cudaGetSymbolAddress((void**)&attn, g_attn);
    cudaGetSymbolAddress((void**)&tmp, g_tmp);
    cudaGetSymbolAddress((void**)&hbuf, g_h);
    cudaGetSymbolAddress((void**)&wqkv, g_wqkv);
    cudaGetSymbolAddress((void**)&wor, g_wor);
    cudaGetSymbolAddress((void**)&projr, g_projr);

    const int smem64 = ((128 + 64) * 36 * 2) * 4;
    const int smemkvf = (96 * 68 + 2 * 32 * 68 + 2 * 32 * 72 + 32 * 104) * 4;
    const int smemattn = (128 * 68 + 2 * 128 * 36 + 2 * 32 * 68 + 2 * 64 * 36 + MPAD + 128) * 4;
    cudaFuncSetAttribute(tc_gemm2<0, 64>, cudaFuncAttributeMaxDynamicSharedMemorySize, smem64);
    cudaFuncSetAttribute(tc_gemm2<3, 64>, cudaFuncAttributeMaxDynamicSharedMemorySize, smem64);
    cudaFuncSetAttribute(tc_kvf, cudaFuncAttributeMaxDynamicSharedMemorySize, smemkvf);
    cudaFuncSetAttribute(tc_attn, cudaFuncAttributeMaxDynamicSharedMemorySize, smemattn);

    cudaMemcpyAsync(out + (size_t)NNODES * FDIM, eattr,
                    (size_t)EEDGE * 8 * sizeof(float), cudaMemcpyDeviceToDevice);

    const int PACKN = NLAYER * (QKF * FDIM + FDIM * FDIM + MPAD * HDIM);
    pack_weights<<<(PACKN + 255) / 256, 256>>>(Wq, Wk, Wv, Wo, pr);
    round_arr<<<(NNODES * FDIM / 4 + 255) / 256, 256>>>(h0, hbuf, NNODES * FDIM / 4);

    const int REDN = NHEAD * MPAD * 64 + NHEAD * MPAD;
    for (int l = 0; l < NLAYER; l++) {
        float* hout = (l == NLAYER - 1) ? out : hbuf;
        tc_gemm2<0, 64><<<dim3(9, NB128), 256, smem64>>>(
            hbuf, FDIM, wqkv + (size_t)l * QKF * FDIM, FDIM, QKF, qkv, QKF, FDIM, nullptr);
        tc_kvf<<<dim3(3, NC, 3), 256, smemkvf>>>(projr + (size_t)l * MPAD * HDIM);
        kv_reduce2<<<(REDN + 255) / 256, 256>>>();
        tc_attn<<<dim3(NB128, 3), 256, smemattn>>>(projr + (size_t)l * MPAD * HDIM);
        tc_gemm2<3, 64><<<dim3(3, NB128), 256, smem64>>>(
            attn, FDIM, wor + (size_t)l * FDIM * FDIM, FDIM, FDIM, tmp, FDIM, FDIM, bo + l * FDIM);
        ln_kernel<<<(NNODES + 3) / 4, 128>>>(tmp, hout, ga + l * FDIM, be + l * FDIM,
                                             (l < NLAYER - 1) ? 1 : 0);
    }
}